// round 12
// baseline (speedup 1.0000x reference)
#include <cuda_runtime.h>
#include <math.h>

// ---------------------------------------------------------------------------
// NNGAT_Net, 2-kernel pipeline:
//  k_pre : blocks 0..511    -> adjacency>0 bitsets (g_adjb)
//          blocks 512..1023 -> h = x@W1 (+es/ed) as a register-tiled GEMM:
//          warp = 32x32 tile, thread = 4x8 register block, x transposed
//          per-k-chunk into padded smem. 3 LDS.128 per 32 FMAs.
//  main  : per-batch GAT1-softmax/agg -> topk -> GAT2 -> topk -> MLP
// Output: logp [512*2] | s1 [512*100] | s2 [512*50]
// ---------------------------------------------------------------------------

namespace {
constexpr int B_    = 512;
constexpr int N_    = 200;
constexpr int IND   = 200;
constexpr int D1_   = 32;
constexpr int D2_   = 32;
constexpr int K1_   = 100;
constexpr int K2_   = 50;
constexpr int NT    = 512;          // main kernel: 16 warps
constexpr int NW    = 16;
constexpr int ALP   = 224;          // padded alpha row (7*32)
constexpr int XTP   = 224;          // xT row pitch (200 + 24 pad)
constexpr float NEGF = -1e9f;

// main-kernel shared memory layout (float indices)
constexpr int OFF_H     = 0;        // 6400: h1 [200x32]; later xk[100x32], xk2[50x32]@+3200
constexpr int OFF_HO    = 6400;     // 6400: hout1 [200x32] -> sH2/sOUT2
constexpr int OFF_AL    = 12800;    // 3584: per-warp alpha rows [16x224]; readout scratch
constexpr int OFF_ES    = 16384;    // 200
constexpr int OFF_ED    = 16584;    // 200
constexpr int OFF_SC    = 16784;    // 200
constexpr int OFF_VAL   = 16984;    // 100
constexpr int OFF_PERM  = 17084;    // 100 (int)
constexpr int OFF_PERM2 = 17184;    // 52  (int)
constexpr int OFF_ADJB  = 17236;    // 1400 (u32): adj bitset [200][7]; later W2 [32x32]
constexpr int OFF_AKB   = 18636;    // 400 (u32)
constexpr int OFF_A2B   = 19036;    // 400 (u32)
constexpr int OFF_Z     = 19436;    // 192
constexpr int OFF_RED   = 19628;    // 32
constexpr int SMEM_FLOATS = 19660;  // 78640 bytes -> 2 CTAs/SM
}

// inter-kernel staging buffers (static device globals: allowed scratch)
__device__ float    g_h[(size_t)B_ * N_ * D1_];   // 13.1 MB
__device__ float    g_es[(size_t)B_ * N_];
__device__ float    g_ed[(size_t)B_ * N_];
__device__ unsigned g_adjb[(size_t)B_ * N_ * 7];  // 2.87 MB

__device__ __forceinline__ float warpMax(float v) {
    #pragma unroll
    for (int o = 16; o > 0; o >>= 1) v = fmaxf(v, __shfl_xor_sync(0xffffffffu, v, o));
    return v;
}
__device__ __forceinline__ float warpSum(float v) {
    #pragma unroll
    for (int o = 16; o > 0; o >>= 1) v += __shfl_xor_sync(0xffffffffu, v, o);
    return v;
}
__device__ __forceinline__ float lrelu02(float x) { return x > 0.f ? x : 0.2f * x; }

// ============ k_pre =========================================================
// blocks [0,512): adjacency bitsets.  blocks [512,1024): register-tiled GEMM
// h = x@W1 for one batch (7 warp-tiles of 32 rows; warp 7 helps staging).
__global__ __launch_bounds__(256, 4)
void k_pre(const float* __restrict__ x, const float* __restrict__ adj,
           const float* __restrict__ W1,
           const float* __restrict__ a1s, const float* __restrict__ a1d)
{
    __shared__ float sW[IND * D1_];       // 25.6 KB
    __shared__ float sXT[32 * XTP];       // 28.7 KB: x^T chunk [k][row], padded

    const int tid  = threadIdx.x;
    const int lane = tid & 31;
    const int wid  = tid >> 5;

    if (blockIdx.x < B_) {
        // ---- adjacency > 0 -> bitsets ----
        const int b = blockIdx.x;
        const float* adjb = adj + (size_t)b * N_ * N_;
        for (int i = wid; i < N_; i += 8) {
            #pragma unroll
            for (int c = 0; c < 7; c++) {
                const int j = c * 32 + lane;
                float w = (j < N_) ? adjb[i * N_ + j] : 0.f;
                unsigned bal = __ballot_sync(0xffffffffu, w > 0.f);
                if (lane == 0) g_adjb[((size_t)b * N_ + i) * 7 + c] = bal;
            }
        }
        return;
    }

    const int b  = blockIdx.x - B_;
    const int tr = lane >> 2;      // 0..7  -> 4-row group within tile
    const int tc = lane & 3;       // 0..3  -> 8-col group

    // load W1; zero the xT pad columns (rows 200..223)
    {
        const float4* w4 = (const float4*)W1;
        float4* d4 = (float4*)sW;
        for (int t = tid; t < IND * D1_ / 4; t += 256) d4[t] = w4[t];
        for (int t = tid; t < 32 * (XTP - N_); t += 256) {
            const int k = t / (XTP - N_), p = t % (XTP - N_);
            sXT[k * XTP + N_ + p] = 0.f;
        }
    }

    float acc[4][8];
    #pragma unroll
    for (int j = 0; j < 4; j++)
        #pragma unroll
        for (int i = 0; i < 8; i++) acc[j][i] = 0.f;

    const float* xb = x + (size_t)b * N_ * IND;

    for (int c = 0; c < 7; c++) {
        const int k0 = c * 32;
        const int kcnt = (c < 6) ? 32 : 8;
        __syncthreads();   // previous chunk's reads done
        // transpose-load chunk: float4 along k
        for (int idx = tid; idx < 50 * kcnt; idx += 256) {
            const int row = idx % 200;
            const int q   = idx / 200;
            float4 v = __ldg((const float4*)(xb + (size_t)row * IND + k0) + q);
            const int k = q * 4;
            sXT[(k + 0) * XTP + row] = v.x;
            sXT[(k + 1) * XTP + row] = v.y;
            sXT[(k + 2) * XTP + row] = v.z;
            sXT[(k + 3) * XTP + row] = v.w;
        }
        __syncthreads();

        if (wid < 7) {
            const float* xbase = sXT + (wid << 5) + (tr << 2);
            #pragma unroll 4
            for (int k = 0; k < kcnt; k++) {
                const float4 xv = *(const float4*)(xbase + k * XTP);
                const float4* wr = (const float4*)(sW + (k0 + k) * D1_);
                const float4 w0 = wr[tc * 2];
                const float4 w1 = wr[tc * 2 + 1];
                acc[0][0] = fmaf(xv.x, w0.x, acc[0][0]);
                acc[0][1] = fmaf(xv.x, w0.y, acc[0][1]);
                acc[0][2] = fmaf(xv.x, w0.z, acc[0][2]);
                acc[0][3] = fmaf(xv.x, w0.w, acc[0][3]);
                acc[0][4] = fmaf(xv.x, w1.x, acc[0][4]);
                acc[0][5] = fmaf(xv.x, w1.y, acc[0][5]);
                acc[0][6] = fmaf(xv.x, w1.z, acc[0][6]);
                acc[0][7] = fmaf(xv.x, w1.w, acc[0][7]);
                acc[1][0] = fmaf(xv.y, w0.x, acc[1][0]);
                acc[1][1] = fmaf(xv.y, w0.y, acc[1][1]);
                acc[1][2] = fmaf(xv.y, w0.z, acc[1][2]);
                acc[1][3] = fmaf(xv.y, w0.w, acc[1][3]);
                acc[1][4] = fmaf(xv.y, w1.x, acc[1][4]);
                acc[1][5] = fmaf(xv.y, w1.y, acc[1][5]);
                acc[1][6] = fmaf(xv.y, w1.z, acc[1][6]);
                acc[1][7] = fmaf(xv.y, w1.w, acc[1][7]);
                acc[2][0] = fmaf(xv.z, w0.x, acc[2][0]);
                acc[2][1] = fmaf(xv.z, w0.y, acc[2][1]);
                acc[2][2] = fmaf(xv.z, w0.z, acc[2][2]);
                acc[2][3] = fmaf(xv.z, w0.w, acc[2][3]);
                acc[2][4] = fmaf(xv.z, w1.x, acc[2][4]);
                acc[2][5] = fmaf(xv.z, w1.y, acc[2][5]);
                acc[2][6] = fmaf(xv.z, w1.z, acc[2][6]);
                acc[2][7] = fmaf(xv.z, w1.w, acc[2][7]);
                acc[3][0] = fmaf(xv.w, w0.x, acc[3][0]);
                acc[3][1] = fmaf(xv.w, w0.y, acc[3][1]);
                acc[3][2] = fmaf(xv.w, w0.z, acc[3][2]);
                acc[3][3] = fmaf(xv.w, w0.w, acc[3][3]);
                acc[3][4] = fmaf(xv.w, w1.x, acc[3][4]);
                acc[3][5] = fmaf(xv.w, w1.y, acc[3][5]);
                acc[3][6] = fmaf(xv.w, w1.z, acc[3][6]);
                acc[3][7] = fmaf(xv.w, w1.w, acc[3][7]);
            }
        }
    }

    // epilogue: store h, es, ed (tile rows beyond 200 have acc==0; skip stores)
    if (wid < 7) {
        const int c0 = tc * 8;
        float4 s0 = __ldg((const float4*)(a1s + c0));
        float4 s1 = __ldg((const float4*)(a1s + c0 + 4));
        float4 d0 = __ldg((const float4*)(a1d + c0));
        float4 d1 = __ldg((const float4*)(a1d + c0 + 4));
        #pragma unroll
        for (int j = 0; j < 4; j++) {
            const int row = (wid << 5) + (tr << 2) + j;
            float pes = acc[j][0] * s0.x + acc[j][1] * s0.y + acc[j][2] * s0.z + acc[j][3] * s0.w
                      + acc[j][4] * s1.x + acc[j][5] * s1.y + acc[j][6] * s1.z + acc[j][7] * s1.w;
            float ped = acc[j][0] * d0.x + acc[j][1] * d0.y + acc[j][2] * d0.z + acc[j][3] * d0.w
                      + acc[j][4] * d1.x + acc[j][5] * d1.y + acc[j][6] * d1.z + acc[j][7] * d1.w;
            pes += __shfl_xor_sync(0xffffffffu, pes, 1);
            pes += __shfl_xor_sync(0xffffffffu, pes, 2);
            ped += __shfl_xor_sync(0xffffffffu, ped, 1);
            ped += __shfl_xor_sync(0xffffffffu, ped, 2);
            if (row < N_) {
                float* hp = g_h + ((size_t)b * N_ + row) * D1_ + c0;
                *(float4*)(hp)     = make_float4(acc[j][0], acc[j][1], acc[j][2], acc[j][3]);
                *(float4*)(hp + 4) = make_float4(acc[j][4], acc[j][5], acc[j][6], acc[j][7]);
                if (tc == 0) {
                    g_es[(size_t)b * N_ + row] = pes;
                    g_ed[(size_t)b * N_ + row] = ped;
                }
            }
        }
    }
}

// ============ main kernel ===================================================
__global__ __launch_bounds__(NT, 2)
void nngat_main(
    const float* __restrict__ W2,    const float* __restrict__ a2s,
    const float* __restrict__ a2d,   const float* __restrict__ b1,
    const float* __restrict__ b2,
    const float* __restrict__ pw1,   const float* __restrict__ pw2,
    const float* __restrict__ fc1_w, const float* __restrict__ fc1_b,
    const float* __restrict__ fc2_w, const float* __restrict__ fc2_b,
    const float* __restrict__ fc3_w, const float* __restrict__ fc3_b,
    const float* __restrict__ bn4_g, const float* __restrict__ bn4_b,
    const float* __restrict__ bn5_g, const float* __restrict__ bn5_b,
    float* __restrict__ out)
{
    extern __shared__ float sm[];
    int*      smi = (int*)sm;
    unsigned* smu = (unsigned*)sm;

    const int b    = blockIdx.x;
    const int tid  = threadIdx.x;
    const int lane = tid & 31;
    const int wid  = tid >> 5;

    // ---- stage h, es/ed, adj bitsets from the pre-kernel; pw norms ----
    {
        const float4* h4 = (const float4*)(g_h + (size_t)b * N_ * D1_);
        float4* d4 = (float4*)(sm + OFF_H);
        for (int t = tid; t < N_ * D1_ / 4; t += NT) d4[t] = h4[t];
    }
    for (int t = tid; t < N_; t += NT) {
        sm[OFF_ES + t] = g_es[(size_t)b * N_ + t];
        sm[OFF_ED + t] = g_ed[(size_t)b * N_ + t];
    }
    for (int t = tid; t < N_ * 7; t += NT)
        smu[OFF_ADJB + t] = g_adjb[(size_t)b * N_ * 7 + t];
    if (wid == 0) {
        float v = pw1[lane];
        float s = warpSum(v * v);
        if (lane == 0) sm[OFF_RED + 0] = sqrtf(s) + 1e-16f;
    }
    if (wid == 1) {
        float v = pw2[lane];
        float s = warpSum(v * v);
        if (lane == 0) sm[OFF_RED + 1] = sqrtf(s) + 1e-16f;
    }
    __syncthreads();

    const float b1_l = __ldg(&b1[lane]);

    // ============ Phase B: GAT1 softmax + sparse agg (bitsets in smem) ======
    {
        float* al = sm + OFF_AL + wid * ALP;
        for (int i = wid; i < N_; i += NW) {
            const float edi = sm[OFF_ED + i];
            unsigned mw[7];
            float alr[7];
            float mx = -INFINITY;
            #pragma unroll
            for (int c = 0; c < 7; c++) {
                unsigned bal = smu[OFF_ADJB + i * 7 + c];
                if ((i >> 5) == c) bal |= 1u << (i & 31);   // self-loop
                mw[c] = bal;
                float lg = NEGF;
                const int j = c * 32 + lane;
                if ((bal >> lane) & 1u) lg = lrelu02(edi + sm[OFF_ES + j]);
                alr[c] = lg;
                mx = fmaxf(mx, lg);
            }
            mx = warpMax(mx);

            float s = 0.f;
            #pragma unroll
            for (int c = 0; c < 7; c++) {
                float e = __expf(alr[c] - mx);    // masked lanes underflow to 0
                al[c * 32 + lane] = e;            // padded row: in-bounds
                s += e;
            }
            s = warpSum(s);
            const float inv = __fdividef(1.f, s);

            float acc0 = 0.f, acc1 = 0.f, acc2 = 0.f, acc3 = 0.f;
            #pragma unroll
            for (int c = 0; c < 7; c++) {
                unsigned w = mw[c];               // warp-uniform
                const float* hb = sm + OFF_H + c * 32 * D1_ + lane;
                const float* ab = al + c * 32;
                while (w) {
                    const int t0 = __ffs(w) - 1; w &= w - 1;
                    acc0 = fmaf(ab[t0], hb[t0 * D1_], acc0);
                    if (!w) break;
                    const int t1 = __ffs(w) - 1; w &= w - 1;
                    acc1 = fmaf(ab[t1], hb[t1 * D1_], acc1);
                    if (!w) break;
                    const int t2 = __ffs(w) - 1; w &= w - 1;
                    acc2 = fmaf(ab[t2], hb[t2 * D1_], acc2);
                    if (!w) break;
                    const int t3 = __ffs(w) - 1; w &= w - 1;
                    acc3 = fmaf(ab[t3], hb[t3 * D1_], acc3);
                }
            }
            sm[OFF_HO + i * D1_ + lane] = ((acc0 + acc1) + (acc2 + acc3)) * inv + b1_l;
        }
    }
    __syncthreads();

    // ============ Phase C: pool-1 scores ====================================
    {
        const float pw1_l = __ldg(&pw1[lane]);
        const float invn1 = __fdividef(1.f, sm[OFF_RED + 0]);
        for (int i = wid; i < N_; i += NW) {
            float s = warpSum(sm[OFF_HO + i * D1_ + lane] * pw1_l);
            if (lane == 0) sm[OFF_SC + i] = __fdividef(1.f, 1.f + __expf(-s * invn1));
        }
    }
    __syncthreads();

    // stable descending rank == jax.lax.top_k order
    if (tid < N_) {
        const float si = sm[OFF_SC + tid];
        int cnt = 0;
        for (int j = 0; j < N_; j++) {
            const float sj = sm[OFF_SC + j];
            cnt += (sj > si) || (sj == si && j < tid);
        }
        if (cnt < K1_) smi[OFF_PERM + cnt] = tid;
    }
    __syncthreads();

    for (int r = tid; r < K1_; r += NT) {
        float v = sm[OFF_SC + smi[OFF_PERM + r]];
        sm[OFF_VAL + r] = v;
        out[512 * 2 + (size_t)b * K1_ + r] = v;
    }
    __syncthreads();

    // gated xk = hout[perm] * vals  (into dead h1 region)
    for (int t = tid; t < K1_ * D1_; t += NT) {
        const int r = t >> 5, d = t & 31;
        sm[OFF_H + t] = sm[OFF_HO + smi[OFF_PERM + r] * D1_ + d] * sm[OFF_VAL + r];
    }
    __syncthreads();

    // x1 readout partials (warps 0-3)
    if (wid < 4) {
        float mx = -INFINITY, s = 0.f;
        for (int r = wid * 25; r < wid * 25 + 25; r++) {
            float v = sm[OFF_H + r * D1_ + lane];
            mx = fmaxf(mx, v);
            s += v;
        }
        sm[OFF_AL + (wid * 2 + 0) * 32 + lane] = mx;
        sm[OFF_AL + (wid * 2 + 1) * 32 + lane] = s;
    }
    // AKB via warp ballot: lane = pooled column
    for (int r = wid; r < K1_; r += NW) {
        const int pr = smi[OFF_PERM + r];
        const unsigned* arow = smu + OFF_ADJB + pr * 7;
        #pragma unroll
        for (int w = 0; w < 4; w++) {
            const int c = w * 32 + lane;
            bool bit = false;
            if (c < K1_) {
                const int pc = smi[OFF_PERM + c];
                bit = (arow[pc >> 5] >> (pc & 31)) & 1u;
            }
            unsigned bal = __ballot_sync(0xffffffffu, bit);
            if (lane == 0) smu[OFF_AKB + r * 4 + w] = bal;
        }
    }
    __syncthreads();   // ADJB dead from here

    // combine x1 partials; a2 = ak | (ak_nz @ ak_nz); stage W2 into ADJB
    if (tid < 32) {
        float mx = fmaxf(fmaxf(sm[OFF_AL + 0 * 32 + lane], sm[OFF_AL + 2 * 32 + lane]),
                         fmaxf(sm[OFF_AL + 4 * 32 + lane], sm[OFF_AL + 6 * 32 + lane]));
        float s = sm[OFF_AL + 1 * 32 + lane] + sm[OFF_AL + 3 * 32 + lane]
                + sm[OFF_AL + 5 * 32 + lane] + sm[OFF_AL + 7 * 32 + lane];
        sm[OFF_Z + lane]      = mx;
        sm[OFF_Z + 32 + lane] = s * (1.f / K1_);
    }
    for (int t = tid; t < K1_ * 4; t += NT) {
        const int r = t >> 2, w = t & 3;
        unsigned acc = smu[OFF_AKB + t];
        #pragma unroll
        for (int kc = 0; kc < 4; kc++) {
            unsigned rw = smu[OFF_AKB + r * 4 + kc];
            while (rw) {
                const int k = __ffs(rw) - 1; rw &= rw - 1;
                acc |= smu[OFF_AKB + (kc * 32 + k) * 4 + w];
            }
        }
        smu[OFF_A2B + t] = acc;
    }
    for (int t = tid; t < D1_ * D2_; t += NT) sm[OFF_ADJB + t] = W2[t];
    __syncthreads();

    // ============ Phase E: GAT2 =============================================
    const float a2s_l = __ldg(&a2s[lane]);
    const float a2d_l = __ldg(&a2d[lane]);
    const float b2_l  = __ldg(&b2[lane]);
    float* sXK   = sm + OFF_H;                 // [100x32]
    float* sH2   = sm + OFF_HO;                // [100x32]
    float* sOUT2 = sm + OFF_HO + K1_ * D2_;    // [100x32]
    float* sW2   = sm + OFF_ADJB;              // [32x32]
    float* sAL2  = sm + OFF_AL;                // [16 x ALP] alpha scratch

    for (int i = wid; i < K1_; i += NW) {
        const float4* xr4 = (const float4*)(sXK + i * D1_);
        float acc = 0.f;
        #pragma unroll
        for (int k4 = 0; k4 < D1_ / 4; k4++) {
            float4 xv = xr4[k4];
            const int k = k4 * 4;
            acc = fmaf(xv.x, sW2[(k + 0) * D2_ + lane], acc);
            acc = fmaf(xv.y, sW2[(k + 1) * D2_ + lane], acc);
            acc = fmaf(xv.z, sW2[(k + 2) * D2_ + lane], acc);
            acc = fmaf(xv.w, sW2[(k + 3) * D2_ + lane], acc);
        }
        sH2[i * D2_ + lane] = acc;
        float es = warpSum(acc * a2s_l);
        float ed = warpSum(acc * a2d_l);
        if (lane == 0) { sm[OFF_ES + i] = es; sm[OFF_ED + i] = ed; }
    }
    __syncthreads();

    // GAT2 attention + aggregation: 2 rows per warp
    for (int g = wid; g < K1_ / 2; g += NW) {
        const int i0 = 2 * g, i1 = i0 + 1;
        const float ed0 = sm[OFF_ED + i0];
        const float ed1 = sm[OFF_ED + i1];
        float* al2 = sAL2 + wid * ALP;
        float alr0[4], alr1[4];
        float mx0 = -INFINITY, mx1 = -INFINITY;
        #pragma unroll
        for (int c = 0; c < 4; c++) {
            const int j = c * 32 + lane;
            float lg0 = NEGF, lg1 = NEGF;
            if (j < K1_) {
                const float esj = sm[OFF_ES + j];
                const unsigned b0 = smu[OFF_A2B + i0 * 4 + c];
                const unsigned b1w = smu[OFF_A2B + i1 * 4 + c];
                if ((j == i0) || ((b0 >> lane) & 1u))  lg0 = lrelu02(ed0 + esj);
                if ((j == i1) || ((b1w >> lane) & 1u)) lg1 = lrelu02(ed1 + esj);
            }
            alr0[c] = lg0; alr1[c] = lg1;
            mx0 = fmaxf(mx0, lg0); mx1 = fmaxf(mx1, lg1);
        }
        mx0 = warpMax(mx0); mx1 = warpMax(mx1);
        float s0 = 0.f, s1 = 0.f;
        #pragma unroll
        for (int c = 0; c < 4; c++) {
            const int j = c * 32 + lane;
            if (j < K1_) {
                float e0 = __expf(alr0[c] - mx0);
                float e1 = __expf(alr1[c] - mx1);
                al2[j] = e0;
                al2[100 + j] = e1;
                s0 += e0; s1 += e1;
            }
        }
        s0 = warpSum(s0); s1 = warpSum(s1);
        const float inv0 = __fdividef(1.f, s0);
        const float inv1 = __fdividef(1.f, s1);

        const float4* a40 = (const float4*)al2;
        const float4* a41 = (const float4*)(al2 + 100);
        float p00 = 0.f, p01 = 0.f, p02 = 0.f, p03 = 0.f;
        float p10 = 0.f, p11 = 0.f, p12 = 0.f, p13 = 0.f;
        #pragma unroll 5
        for (int j4 = 0; j4 < K1_ / 4; j4++) {
            float4 a0 = a40[j4];
            float4 a1 = a41[j4];
            const int j = j4 * 4;
            float h0 = sH2[(j + 0) * D2_ + lane];
            float h1 = sH2[(j + 1) * D2_ + lane];
            float h2 = sH2[(j + 2) * D2_ + lane];
            float h3 = sH2[(j + 3) * D2_ + lane];
            p00 = fmaf(a0.x, h0, p00); p01 = fmaf(a0.y, h1, p01);
            p02 = fmaf(a0.z, h2, p02); p03 = fmaf(a0.w, h3, p03);
            p10 = fmaf(a1.x, h0, p10); p11 = fmaf(a1.y, h1, p11);
            p12 = fmaf(a1.z, h2, p12); p13 = fmaf(a1.w, h3, p13);
        }
        sOUT2[i0 * D2_ + lane] = ((p00 + p01) + (p02 + p03)) * inv0 + b2_l;
        sOUT2[i1 * D2_ + lane] = ((p10 + p11) + (p12 + p13)) * inv1 + b2_l;
    }
    __syncthreads();

    // ============ Phase F: pool-2 ===========================================
    {
        const float pw2_l = __ldg(&pw2[lane]);
        const float invn2 = __fdividef(1.f, sm[OFF_RED + 1]);
        for (int i = wid; i < K1_; i += NW) {
            float s = warpSum(sOUT2[i * D2_ + lane] * pw2_l);
            if (lane == 0) sm[OFF_SC + i] = __fdividef(1.f, 1.f + __expf(-s * invn2));
        }
    }
    __syncthreads();

    if (tid < K1_) {
        const float si = sm[OFF_SC + tid];
        int cnt = 0;
        for (int j = 0; j < K1_; j++) {
            const float sj = sm[OFF_SC + j];
            cnt += (sj > si) || (sj == si && j < tid);
        }
        if (cnt < K2_) smi[OFF_PERM2 + cnt] = tid;
    }
    __syncthreads();

    for (int r = tid; r < K2_; r += NT) {
        float v = sm[OFF_SC + smi[OFF_PERM2 + r]];
        sm[OFF_VAL + r] = v;
        out[512 * 2 + 512 * K1_ + (size_t)b * K2_ + r] = v;
    }
    __syncthreads();

    float* sXK2 = sm + OFF_H + K1_ * D1_;   // [50x32]
    for (int t = tid; t < K2_ * D2_; t += NT) {
        const int r = t >> 5, d = t & 31;
        sXK2[t] = sOUT2[smi[OFF_PERM2 + r] * D2_ + d] * sm[OFF_VAL + r];
    }
    __syncthreads();

    // x2 readout partials (warps 0-1)
    if (wid < 2) {
        float mx = -INFINITY, s = 0.f;
        for (int r = wid * 25; r < wid * 25 + 25; r++) {
            float v = sXK2[r * D2_ + lane];
            mx = fmaxf(mx, v);
            s += v;
        }
        sm[OFF_AL + (wid * 2 + 0) * 32 + lane] = mx;
        sm[OFF_AL + (wid * 2 + 1) * 32 + lane] = s;
    }
    __syncthreads();
    if (tid < 32) {
        float mx = fmaxf(sm[OFF_AL + 0 * 32 + lane], sm[OFF_AL + 2 * 32 + lane]);
        float s  = sm[OFF_AL + 1 * 32 + lane] + sm[OFF_AL + 3 * 32 + lane];
        sm[OFF_Z + 64 + lane] = mx;
        sm[OFF_Z + 96 + lane] = s * (1.f / K2_);
    }
    __syncthreads();

    // ============ Phase G: MLP head (warp 0) ================================
    if (wid == 0) {
        const float invbn = 1.0f / sqrtf(1.0f + 1e-5f);
        float acc = __ldg(&fc1_b[lane]);
        #pragma unroll 4
        for (int k = 0; k < 128; k++) acc = fmaf(sm[OFF_Z + k], __ldg(&fc1_w[k * 32 + lane]), acc);
        acc = fmaxf(acc, 0.f);
        sm[OFF_Z + 128 + lane] = __ldg(&bn4_g[lane]) * acc * invbn + __ldg(&bn4_b[lane]);
        __syncwarp();
        if (lane < 8) {
            float a = __ldg(&fc2_b[lane]);
            #pragma unroll
            for (int k = 0; k < 32; k++) a = fmaf(sm[OFF_Z + 128 + k], __ldg(&fc2_w[k * 8 + lane]), a);
            a = fmaxf(a, 0.f);
            sm[OFF_Z + 160 + lane] = __ldg(&bn5_g[lane]) * a * invbn + __ldg(&bn5_b[lane]);
        }
        __syncwarp();
        if (lane < 2) {
            float a = __ldg(&fc3_b[lane]);
            #pragma unroll
            for (int k = 0; k < 8; k++) a = fmaf(sm[OFF_Z + 160 + k], __ldg(&fc3_w[k * 2 + lane]), a);
            sm[OFF_Z + 170 + lane] = a;
        }
        __syncwarp();
        if (lane == 0) {
            float l0 = sm[OFF_Z + 170], l1 = sm[OFF_Z + 171];
            float m = fmaxf(l0, l1);
            float lse = m + __logf(__expf(l0 - m) + __expf(l1 - m));
            out[(size_t)b * 2 + 0] = l0 - lse;
            out[(size_t)b * 2 + 1] = l1 - lse;
        }
    }
}

extern "C" void kernel_launch(void* const* d_in, const int* in_sizes, int n_in,
                              void* d_out, int out_size) {
    const float* x     = (const float*)d_in[0];
    const float* adj   = (const float*)d_in[1];
    const float* W1    = (const float*)d_in[2];
    const float* a1s   = (const float*)d_in[3];
    const float* a1d   = (const float*)d_in[4];
    const float* b1    = (const float*)d_in[5];
    const float* W2    = (const float*)d_in[6];
    const float* a2s   = (const float*)d_in[7];
    const float* a2d   = (const float*)d_in[8];
    const float* b2    = (const float*)d_in[9];
    const float* pw1   = (const float*)d_in[10];
    const float* pw2   = (const float*)d_in[11];
    const float* fc1w  = (const float*)d_in[12];
    const float* fc1b  = (const float*)d_in[13];
    const float* fc2w  = (const float*)d_in[14];
    const float* fc2b  = (const float*)d_in[15];
    const float* fc3w  = (const float*)d_in[16];
    const float* fc3b  = (const float*)d_in[17];
    const float* bn4g  = (const float*)d_in[18];
    const float* bn4b  = (const float*)d_in[19];
    const float* bn5g  = (const float*)d_in[20];
    const float* bn5b  = (const float*)d_in[21];
    float* out = (float*)d_out;

    k_pre<<<B_ * 2, 256>>>(x, adj, W1, a1s, a1d);

    const int smem_bytes = SMEM_FLOATS * (int)sizeof(float);
    cudaFuncSetAttribute(nngat_main, cudaFuncAttributeMaxDynamicSharedMemorySize,
                         smem_bytes);
    nngat_main<<<B_, NT, smem_bytes>>>(
        W2, a2s, a2d, b1, b2, pw1, pw2,
        fc1w, fc1b, fc2w, fc2b, fc3w, fc3b, bn4g, bn4b, bn5g, bn5b, out);
}

// round 14
// speedup vs baseline: 1.2344x; 1.2344x over previous
#include <cuda_runtime.h>
#include <math.h>

// ---------------------------------------------------------------------------
// NNGAT_Net, 2-kernel pipeline:
//  k_pre : blocks 0..511    -> adjacency>0 bitsets (g_adjb)
//          blocks 512..1023 -> h = x@W1 (+es/ed) register-tiled GEMM:
//          warp = 32x32 tile, thread = 4x8 block; x staged ROW-MAJOR into
//          sX[224][33] (coalesced LDG, conflict-free LDS) per 32-k chunk.
//          (224 rows: pad rows 200..223 zeroed; their results discarded.)
//  main  : per-batch GAT1-softmax/agg -> topk -> GAT2 -> topk -> MLP
// Output: logp [512*2] | s1 [512*100] | s2 [512*50]
// ---------------------------------------------------------------------------

namespace {
constexpr int B_    = 512;
constexpr int N_    = 200;
constexpr int IND   = 200;
constexpr int D1_   = 32;
constexpr int D2_   = 32;
constexpr int K1_   = 100;
constexpr int K2_   = 50;
constexpr int NT    = 512;          // main kernel: 16 warps
constexpr int NW    = 16;
constexpr int ALP   = 224;          // padded alpha row (7*32)
constexpr int XP    = 33;           // sX chunk pitch (32 + 1): conflict-free
constexpr int XROWS = 224;          // 7 warps x 32 rows (200 real + 24 pad)
constexpr float NEGF = -1e9f;

// main-kernel shared memory layout (float indices)
constexpr int OFF_H     = 0;        // 6400: h1 [200x32]; later xk[100x32], xk2[50x32]@+3200
constexpr int OFF_HO    = 6400;     // 6400: hout1 [200x32] -> sH2/sOUT2
constexpr int OFF_AL    = 12800;    // 3584: per-warp alpha rows [16x224]; readout scratch
constexpr int OFF_ES    = 16384;    // 200
constexpr int OFF_ED    = 16584;    // 200
constexpr int OFF_SC    = 16784;    // 200
constexpr int OFF_VAL   = 16984;    // 100
constexpr int OFF_PERM  = 17084;    // 100 (int)
constexpr int OFF_PERM2 = 17184;    // 52  (int)
constexpr int OFF_ADJB  = 17236;    // 1400 (u32): adj bitset [200][7]; later W2 [32x32]
constexpr int OFF_AKB   = 18636;    // 400 (u32)
constexpr int OFF_A2B   = 19036;    // 400 (u32)
constexpr int OFF_Z     = 19436;    // 192
constexpr int OFF_RED   = 19628;    // 32
constexpr int SMEM_FLOATS = 19660;  // 78640 bytes -> 2 CTAs/SM
}

// inter-kernel staging buffers (static device globals: allowed scratch)
__device__ float    g_h[(size_t)B_ * N_ * D1_];   // 13.1 MB
__device__ float    g_es[(size_t)B_ * N_];
__device__ float    g_ed[(size_t)B_ * N_];
__device__ unsigned g_adjb[(size_t)B_ * N_ * 7];  // 2.87 MB

__device__ __forceinline__ float warpMax(float v) {
    #pragma unroll
    for (int o = 16; o > 0; o >>= 1) v = fmaxf(v, __shfl_xor_sync(0xffffffffu, v, o));
    return v;
}
__device__ __forceinline__ float warpSum(float v) {
    #pragma unroll
    for (int o = 16; o > 0; o >>= 1) v += __shfl_xor_sync(0xffffffffu, v, o);
    return v;
}
__device__ __forceinline__ float lrelu02(float x) { return x > 0.f ? x : 0.2f * x; }

// ============ k_pre =========================================================
__global__ __launch_bounds__(256, 4)
void k_pre(const float* __restrict__ x, const float* __restrict__ adj,
           const float* __restrict__ W1,
           const float* __restrict__ a1s, const float* __restrict__ a1d)
{
    __shared__ float sW[IND * D1_];      // 25.6 KB
    __shared__ float sX[XROWS * XP];     // 29.6 KB: row-major chunk [224][33]

    const int tid  = threadIdx.x;
    const int lane = tid & 31;
    const int wid  = tid >> 5;

    if (blockIdx.x < B_) {
        // ---- adjacency > 0 -> bitsets ----
        const int b = blockIdx.x;
        const float* adjb = adj + (size_t)b * N_ * N_;
        for (int i = wid; i < N_; i += 8) {
            #pragma unroll
            for (int c = 0; c < 7; c++) {
                const int j = c * 32 + lane;
                float w = (j < N_) ? adjb[i * N_ + j] : 0.f;
                unsigned bal = __ballot_sync(0xffffffffu, w > 0.f);
                if (lane == 0) g_adjb[((size_t)b * N_ + i) * 7 + c] = bal;
            }
        }
        return;
    }

    const int b  = blockIdx.x - B_;
    const int tr = lane >> 2;      // 0..7  -> 4-row group within tile
    const int tc = lane & 3;       // 0..3  -> 8-col group

    {
        const float4* w4 = (const float4*)W1;
        float4* d4 = (float4*)sW;
        for (int t = tid; t < IND * D1_ / 4; t += 256) d4[t] = w4[t];
        // zero pad rows 200..223 (their accs are discarded, but keep finite)
        for (int t = tid; t < (XROWS - N_) * XP; t += 256)
            sX[N_ * XP + t] = 0.f;
    }

    float acc[4][8];
    #pragma unroll
    for (int j = 0; j < 4; j++)
        #pragma unroll
        for (int i = 0; i < 8; i++) acc[j][i] = 0.f;

    const float* xb = x + (size_t)b * N_ * IND;

    for (int c = 0; c < 7; c++) {
        const int k0 = c * 32;
        const int kcnt = (c < 6) ? 32 : 8;
        __syncthreads();   // previous chunk's reads done (covers W/pad init at c=0)

        // stage chunk row-major, coalesced: lane covers consecutive float4s
        if (c < 6) {
            for (int idx = tid; idx < N_ * 8; idx += 256) {
                const int row = idx >> 3, q = idx & 7;
                float4 v = __ldg((const float4*)(xb + (size_t)row * IND + k0) + q);
                float* d = sX + row * XP + 4 * q;
                d[0] = v.x; d[1] = v.y; d[2] = v.z; d[3] = v.w;
            }
        } else {
            for (int idx = tid; idx < N_ * 2; idx += 256) {
                const int row = idx >> 1, q = idx & 1;
                float4 v = __ldg((const float4*)(xb + (size_t)row * IND + k0) + q);
                float* d = sX + row * XP + 4 * q;
                d[0] = v.x; d[1] = v.y; d[2] = v.z; d[3] = v.w;
            }
        }
        __syncthreads();

        if (wid < 7) {
            const float* x0 = sX + (wid * 32 + tr * 4 + 0) * XP;
            const float* x1 = sX + (wid * 32 + tr * 4 + 1) * XP;
            const float* x2 = sX + (wid * 32 + tr * 4 + 2) * XP;
            const float* x3 = sX + (wid * 32 + tr * 4 + 3) * XP;
            #pragma unroll 4
            for (int k = 0; k < kcnt; k++) {
                const float xv0 = x0[k];
                const float xv1 = x1[k];
                const float xv2 = x2[k];
                const float xv3 = x3[k];
                const float4* wr = (const float4*)(sW + (k0 + k) * D1_);
                const float4 w0 = wr[tc * 2];
                const float4 w1 = wr[tc * 2 + 1];
                acc[0][0] = fmaf(xv0, w0.x, acc[0][0]);
                acc[0][1] = fmaf(xv0, w0.y, acc[0][1]);
                acc[0][2] = fmaf(xv0, w0.z, acc[0][2]);
                acc[0][3] = fmaf(xv0, w0.w, acc[0][3]);
                acc[0][4] = fmaf(xv0, w1.x, acc[0][4]);
                acc[0][5] = fmaf(xv0, w1.y, acc[0][5]);
                acc[0][6] = fmaf(xv0, w1.z, acc[0][6]);
                acc[0][7] = fmaf(xv0, w1.w, acc[0][7]);
                acc[1][0] = fmaf(xv1, w0.x, acc[1][0]);
                acc[1][1] = fmaf(xv1, w0.y, acc[1][1]);
                acc[1][2] = fmaf(xv1, w0.z, acc[1][2]);
                acc[1][3] = fmaf(xv1, w0.w, acc[1][3]);
                acc[1][4] = fmaf(xv1, w1.x, acc[1][4]);
                acc[1][5] = fmaf(xv1, w1.y, acc[1][5]);
                acc[1][6] = fmaf(xv1, w1.z, acc[1][6]);
                acc[1][7] = fmaf(xv1, w1.w, acc[1][7]);
                acc[2][0] = fmaf(xv2, w0.x, acc[2][0]);
                acc[2][1] = fmaf(xv2, w0.y, acc[2][1]);
                acc[2][2] = fmaf(xv2, w0.z, acc[2][2]);
                acc[2][3] = fmaf(xv2, w0.w, acc[2][3]);
                acc[2][4] = fmaf(xv2, w1.x, acc[2][4]);
                acc[2][5] = fmaf(xv2, w1.y, acc[2][5]);
                acc[2][6] = fmaf(xv2, w1.z, acc[2][6]);
                acc[2][7] = fmaf(xv2, w1.w, acc[2][7]);
                acc[3][0] = fmaf(xv3, w0.x, acc[3][0]);
                acc[3][1] = fmaf(xv3, w0.y, acc[3][1]);
                acc[3][2] = fmaf(xv3, w0.z, acc[3][2]);
                acc[3][3] = fmaf(xv3, w0.w, acc[3][3]);
                acc[3][4] = fmaf(xv3, w1.x, acc[3][4]);
                acc[3][5] = fmaf(xv3, w1.y, acc[3][5]);
                acc[3][6] = fmaf(xv3, w1.z, acc[3][6]);
                acc[3][7] = fmaf(xv3, w1.w, acc[3][7]);
            }
        }
    }

    // epilogue: store h, es, ed (rows >= 200 guarded out)
    if (wid < 7) {
        const int c0 = tc * 8;
        float4 s0 = __ldg((const float4*)(a1s + c0));
        float4 s1 = __ldg((const float4*)(a1s + c0 + 4));
        float4 d0 = __ldg((const float4*)(a1d + c0));
        float4 d1 = __ldg((const float4*)(a1d + c0 + 4));
        #pragma unroll
        for (int j = 0; j < 4; j++) {
            const int row = (wid << 5) + (tr << 2) + j;
            float pes = acc[j][0] * s0.x + acc[j][1] * s0.y + acc[j][2] * s0.z + acc[j][3] * s0.w
                      + acc[j][4] * s1.x + acc[j][5] * s1.y + acc[j][6] * s1.z + acc[j][7] * s1.w;
            float ped = acc[j][0] * d0.x + acc[j][1] * d0.y + acc[j][2] * d0.z + acc[j][3] * d0.w
                      + acc[j][4] * d1.x + acc[j][5] * d1.y + acc[j][6] * d1.z + acc[j][7] * d1.w;
            pes += __shfl_xor_sync(0xffffffffu, pes, 1);
            pes += __shfl_xor_sync(0xffffffffu, pes, 2);
            ped += __shfl_xor_sync(0xffffffffu, ped, 1);
            ped += __shfl_xor_sync(0xffffffffu, ped, 2);
            if (row < N_) {
                float* hp = g_h + ((size_t)b * N_ + row) * D1_ + c0;
                *(float4*)(hp)     = make_float4(acc[j][0], acc[j][1], acc[j][2], acc[j][3]);
                *(float4*)(hp + 4) = make_float4(acc[j][4], acc[j][5], acc[j][6], acc[j][7]);
                if (tc == 0) {
                    g_es[(size_t)b * N_ + row] = pes;
                    g_ed[(size_t)b * N_ + row] = ped;
                }
            }
        }
    }
}

// ============ main kernel ===================================================
__global__ __launch_bounds__(NT, 2)
void nngat_main(
    const float* __restrict__ W2,    const float* __restrict__ a2s,
    const float* __restrict__ a2d,   const float* __restrict__ b1,
    const float* __restrict__ b2,
    const float* __restrict__ pw1,   const float* __restrict__ pw2,
    const float* __restrict__ fc1_w, const float* __restrict__ fc1_b,
    const float* __restrict__ fc2_w, const float* __restrict__ fc2_b,
    const float* __restrict__ fc3_w, const float* __restrict__ fc3_b,
    const float* __restrict__ bn4_g, const float* __restrict__ bn4_b,
    const float* __restrict__ bn5_g, const float* __restrict__ bn5_b,
    float* __restrict__ out)
{
    extern __shared__ float sm[];
    int*      smi = (int*)sm;
    unsigned* smu = (unsigned*)sm;

    const int b    = blockIdx.x;
    const int tid  = threadIdx.x;
    const int lane = tid & 31;
    const int wid  = tid >> 5;

    // ---- stage h, es/ed, adj bitsets from the pre-kernel; pw norms ----
    {
        const float4* h4 = (const float4*)(g_h + (size_t)b * N_ * D1_);
        float4* d4 = (float4*)(sm + OFF_H);
        for (int t = tid; t < N_ * D1_ / 4; t += NT) d4[t] = h4[t];
    }
    for (int t = tid; t < N_; t += NT) {
        sm[OFF_ES + t] = g_es[(size_t)b * N_ + t];
        sm[OFF_ED + t] = g_ed[(size_t)b * N_ + t];
    }
    for (int t = tid; t < N_ * 7; t += NT)
        smu[OFF_ADJB + t] = g_adjb[(size_t)b * N_ * 7 + t];
    if (wid == 0) {
        float v = pw1[lane];
        float s = warpSum(v * v);
        if (lane == 0) sm[OFF_RED + 0] = sqrtf(s) + 1e-16f;
    }
    if (wid == 1) {
        float v = pw2[lane];
        float s = warpSum(v * v);
        if (lane == 0) sm[OFF_RED + 1] = sqrtf(s) + 1e-16f;
    }
    __syncthreads();

    const float b1_l = __ldg(&b1[lane]);

    // ============ Phase B: GAT1 softmax + sparse agg (bitsets in smem) ======
    {
        float* al = sm + OFF_AL + wid * ALP;
        for (int i = wid; i < N_; i += NW) {
            const float edi = sm[OFF_ED + i];
            unsigned mw[7];
            float alr[7];
            float mx = -INFINITY;
            #pragma unroll
            for (int c = 0; c < 7; c++) {
                unsigned bal = smu[OFF_ADJB + i * 7 + c];
                if ((i >> 5) == c) bal |= 1u << (i & 31);   // self-loop
                mw[c] = bal;
                float lg = NEGF;
                const int j = c * 32 + lane;
                if ((bal >> lane) & 1u) lg = lrelu02(edi + sm[OFF_ES + j]);
                alr[c] = lg;
                mx = fmaxf(mx, lg);
            }
            mx = warpMax(mx);

            float s = 0.f;
            #pragma unroll
            for (int c = 0; c < 7; c++) {
                float e = __expf(alr[c] - mx);    // masked lanes underflow to 0
                al[c * 32 + lane] = e;            // padded row: in-bounds
                s += e;
            }
            s = warpSum(s);
            const float inv = __fdividef(1.f, s);

            float acc0 = 0.f, acc1 = 0.f, acc2 = 0.f, acc3 = 0.f;
            #pragma unroll
            for (int c = 0; c < 7; c++) {
                unsigned w = mw[c];               // warp-uniform
                const float* hb = sm + OFF_H + c * 32 * D1_ + lane;
                const float* ab = al + c * 32;
                while (w) {
                    const int t0 = __ffs(w) - 1; w &= w - 1;
                    acc0 = fmaf(ab[t0], hb[t0 * D1_], acc0);
                    if (!w) break;
                    const int t1 = __ffs(w) - 1; w &= w - 1;
                    acc1 = fmaf(ab[t1], hb[t1 * D1_], acc1);
                    if (!w) break;
                    const int t2 = __ffs(w) - 1; w &= w - 1;
                    acc2 = fmaf(ab[t2], hb[t2 * D1_], acc2);
                    if (!w) break;
                    const int t3 = __ffs(w) - 1; w &= w - 1;
                    acc3 = fmaf(ab[t3], hb[t3 * D1_], acc3);
                }
            }
            sm[OFF_HO + i * D1_ + lane] = ((acc0 + acc1) + (acc2 + acc3)) * inv + b1_l;
        }
    }
    __syncthreads();

    // ============ Phase C: pool-1 scores ====================================
    {
        const float pw1_l = __ldg(&pw1[lane]);
        const float invn1 = __fdividef(1.f, sm[OFF_RED + 0]);
        for (int i = wid; i < N_; i += NW) {
            float s = warpSum(sm[OFF_HO + i * D1_ + lane] * pw1_l);
            if (lane == 0) sm[OFF_SC + i] = __fdividef(1.f, 1.f + __expf(-s * invn1));
        }
    }
    __syncthreads();

    // stable descending rank == jax.lax.top_k order
    if (tid < N_) {
        const float si = sm[OFF_SC + tid];
        int cnt = 0;
        for (int j = 0; j < N_; j++) {
            const float sj = sm[OFF_SC + j];
            cnt += (sj > si) || (sj == si && j < tid);
        }
        if (cnt < K1_) smi[OFF_PERM + cnt] = tid;
    }
    __syncthreads();

    for (int r = tid; r < K1_; r += NT) {
        float v = sm[OFF_SC + smi[OFF_PERM + r]];
        sm[OFF_VAL + r] = v;
        out[512 * 2 + (size_t)b * K1_ + r] = v;
    }
    __syncthreads();

    // gated xk = hout[perm] * vals  (into dead h1 region)
    for (int t = tid; t < K1_ * D1_; t += NT) {
        const int r = t >> 5, d = t & 31;
        sm[OFF_H + t] = sm[OFF_HO + smi[OFF_PERM + r] * D1_ + d] * sm[OFF_VAL + r];
    }
    __syncthreads();

    // x1 readout partials (warps 0-3)
    if (wid < 4) {
        float mx = -INFINITY, s = 0.f;
        for (int r = wid * 25; r < wid * 25 + 25; r++) {
            float v = sm[OFF_H + r * D1_ + lane];
            mx = fmaxf(mx, v);
            s += v;
        }
        sm[OFF_AL + (wid * 2 + 0) * 32 + lane] = mx;
        sm[OFF_AL + (wid * 2 + 1) * 32 + lane] = s;
    }
    // AKB via warp ballot: lane = pooled column
    for (int r = wid; r < K1_; r += NW) {
        const int pr = smi[OFF_PERM + r];
        const unsigned* arow = smu + OFF_ADJB + pr * 7;
        #pragma unroll
        for (int w = 0; w < 4; w++) {
            const int c = w * 32 + lane;
            bool bit = false;
            if (c < K1_) {
                const int pc = smi[OFF_PERM + c];
                bit = (arow[pc >> 5] >> (pc & 31)) & 1u;
            }
            unsigned bal = __ballot_sync(0xffffffffu, bit);
            if (lane == 0) smu[OFF_AKB + r * 4 + w] = bal;
        }
    }
    __syncthreads();   // ADJB dead from here

    // combine x1 partials; a2 = ak | (ak_nz @ ak_nz); stage W2 into ADJB
    if (tid < 32) {
        float mx = fmaxf(fmaxf(sm[OFF_AL + 0 * 32 + lane], sm[OFF_AL + 2 * 32 + lane]),
                         fmaxf(sm[OFF_AL + 4 * 32 + lane], sm[OFF_AL + 6 * 32 + lane]));
        float s = sm[OFF_AL + 1 * 32 + lane] + sm[OFF_AL + 3 * 32 + lane]
                + sm[OFF_AL + 5 * 32 + lane] + sm[OFF_AL + 7 * 32 + lane];
        sm[OFF_Z + lane]      = mx;
        sm[OFF_Z + 32 + lane] = s * (1.f / K1_);
    }
    for (int t = tid; t < K1_ * 4; t += NT) {
        const int r = t >> 2, w = t & 3;
        unsigned acc = smu[OFF_AKB + t];
        #pragma unroll
        for (int kc = 0; kc < 4; kc++) {
            unsigned rw = smu[OFF_AKB + r * 4 + kc];
            while (rw) {
                const int k = __ffs(rw) - 1; rw &= rw - 1;
                acc |= smu[OFF_AKB + (kc * 32 + k) * 4 + w];
            }
        }
        smu[OFF_A2B + t] = acc;
    }
    for (int t = tid; t < D1_ * D2_; t += NT) sm[OFF_ADJB + t] = W2[t];
    __syncthreads();

    // ============ Phase E: GAT2 =============================================
    const float a2s_l = __ldg(&a2s[lane]);
    const float a2d_l = __ldg(&a2d[lane]);
    const float b2_l  = __ldg(&b2[lane]);
    float* sXK   = sm + OFF_H;                 // [100x32]
    float* sH2   = sm + OFF_HO;                // [100x32]
    float* sOUT2 = sm + OFF_HO + K1_ * D2_;    // [100x32]
    float* sW2   = sm + OFF_ADJB;              // [32x32]
    float* sAL2  = sm + OFF_AL;                // [16 x ALP] alpha scratch

    for (int i = wid; i < K1_; i += NW) {
        const float4* xr4 = (const float4*)(sXK + i * D1_);
        float acc = 0.f;
        #pragma unroll
        for (int k4 = 0; k4 < D1_ / 4; k4++) {
            float4 xv = xr4[k4];
            const int k = k4 * 4;
            acc = fmaf(xv.x, sW2[(k + 0) * D2_ + lane], acc);
            acc = fmaf(xv.y, sW2[(k + 1) * D2_ + lane], acc);
            acc = fmaf(xv.z, sW2[(k + 2) * D2_ + lane], acc);
            acc = fmaf(xv.w, sW2[(k + 3) * D2_ + lane], acc);
        }
        sH2[i * D2_ + lane] = acc;
        float es = warpSum(acc * a2s_l);
        float ed = warpSum(acc * a2d_l);
        if (lane == 0) { sm[OFF_ES + i] = es; sm[OFF_ED + i] = ed; }
    }
    __syncthreads();

    // GAT2 attention + aggregation: 2 rows per warp
    for (int g = wid; g < K1_ / 2; g += NW) {
        const int i0 = 2 * g, i1 = i0 + 1;
        const float ed0 = sm[OFF_ED + i0];
        const float ed1 = sm[OFF_ED + i1];
        float* al2 = sAL2 + wid * ALP;
        float alr0[4], alr1[4];
        float mx0 = -INFINITY, mx1 = -INFINITY;
        #pragma unroll
        for (int c = 0; c < 4; c++) {
            const int j = c * 32 + lane;
            float lg0 = NEGF, lg1 = NEGF;
            if (j < K1_) {
                const float esj = sm[OFF_ES + j];
                const unsigned b0 = smu[OFF_A2B + i0 * 4 + c];
                const unsigned b1w = smu[OFF_A2B + i1 * 4 + c];
                if ((j == i0) || ((b0 >> lane) & 1u))  lg0 = lrelu02(ed0 + esj);
                if ((j == i1) || ((b1w >> lane) & 1u)) lg1 = lrelu02(ed1 + esj);
            }
            alr0[c] = lg0; alr1[c] = lg1;
            mx0 = fmaxf(mx0, lg0); mx1 = fmaxf(mx1, lg1);
        }
        mx0 = warpMax(mx0); mx1 = warpMax(mx1);
        float s0 = 0.f, s1 = 0.f;
        #pragma unroll
        for (int c = 0; c < 4; c++) {
            const int j = c * 32 + lane;
            if (j < K1_) {
                float e0 = __expf(alr0[c] - mx0);
                float e1 = __expf(alr1[c] - mx1);
                al2[j] = e0;
                al2[100 + j] = e1;
                s0 += e0; s1 += e1;
            }
        }
        s0 = warpSum(s0); s1 = warpSum(s1);
        const float inv0 = __fdividef(1.f, s0);
        const float inv1 = __fdividef(1.f, s1);

        const float4* a40 = (const float4*)al2;
        const float4* a41 = (const float4*)(al2 + 100);
        float p00 = 0.f, p01 = 0.f, p02 = 0.f, p03 = 0.f;
        float p10 = 0.f, p11 = 0.f, p12 = 0.f, p13 = 0.f;
        #pragma unroll 5
        for (int j4 = 0; j4 < K1_ / 4; j4++) {
            float4 a0 = a40[j4];
            float4 a1 = a41[j4];
            const int j = j4 * 4;
            float h0 = sH2[(j + 0) * D2_ + lane];
            float h1 = sH2[(j + 1) * D2_ + lane];
            float h2 = sH2[(j + 2) * D2_ + lane];
            float h3 = sH2[(j + 3) * D2_ + lane];
            p00 = fmaf(a0.x, h0, p00); p01 = fmaf(a0.y, h1, p01);
            p02 = fmaf(a0.z, h2, p02); p03 = fmaf(a0.w, h3, p03);
            p10 = fmaf(a1.x, h0, p10); p11 = fmaf(a1.y, h1, p11);
            p12 = fmaf(a1.z, h2, p12); p13 = fmaf(a1.w, h3, p13);
        }
        sOUT2[i0 * D2_ + lane] = ((p00 + p01) + (p02 + p03)) * inv0 + b2_l;
        sOUT2[i1 * D2_ + lane] = ((p10 + p11) + (p12 + p13)) * inv1 + b2_l;
    }
    __syncthreads();

    // ============ Phase F: pool-2 ===========================================
    {
        const float pw2_l = __ldg(&pw2[lane]);
        const float invn2 = __fdividef(1.f, sm[OFF_RED + 1]);
        for (int i = wid; i < K1_; i += NW) {
            float s = warpSum(sOUT2[i * D2_ + lane] * pw2_l);
            if (lane == 0) sm[OFF_SC + i] = __fdividef(1.f, 1.f + __expf(-s * invn2));
        }
    }
    __syncthreads();

    if (tid < K1_) {
        const float si = sm[OFF_SC + tid];
        int cnt = 0;
        for (int j = 0; j < K1_; j++) {
            const float sj = sm[OFF_SC + j];
            cnt += (sj > si) || (sj == si && j < tid);
        }
        if (cnt < K2_) smi[OFF_PERM2 + cnt] = tid;
    }
    __syncthreads();

    for (int r = tid; r < K2_; r += NT) {
        float v = sm[OFF_SC + smi[OFF_PERM2 + r]];
        sm[OFF_VAL + r] = v;
        out[512 * 2 + 512 * K1_ + (size_t)b * K2_ + r] = v;
    }
    __syncthreads();

    float* sXK2 = sm + OFF_H + K1_ * D1_;   // [50x32]
    for (int t = tid; t < K2_ * D2_; t += NT) {
        const int r = t >> 5, d = t & 31;
        sXK2[t] = sOUT2[smi[OFF_PERM2 + r] * D2_ + d] * sm[OFF_VAL + r];
    }
    __syncthreads();

    // x2 readout partials (warps 0-1)
    if (wid < 2) {
        float mx = -INFINITY, s = 0.f;
        for (int r = wid * 25; r < wid * 25 + 25; r++) {
            float v = sXK2[r * D2_ + lane];
            mx = fmaxf(mx, v);
            s += v;
        }
        sm[OFF_AL + (wid * 2 + 0) * 32 + lane] = mx;
        sm[OFF_AL + (wid * 2 + 1) * 32 + lane] = s;
    }
    __syncthreads();
    if (tid < 32) {
        float mx = fmaxf(sm[OFF_AL + 0 * 32 + lane], sm[OFF_AL + 2 * 32 + lane]);
        float s  = sm[OFF_AL + 1 * 32 + lane] + sm[OFF_AL + 3 * 32 + lane];
        sm[OFF_Z + 64 + lane] = mx;
        sm[OFF_Z + 96 + lane] = s * (1.f / K2_);
    }
    __syncthreads();

    // ============ Phase G: MLP head (warp 0) ================================
    if (wid == 0) {
        const float invbn = 1.0f / sqrtf(1.0f + 1e-5f);
        float acc = __ldg(&fc1_b[lane]);
        #pragma unroll 4
        for (int k = 0; k < 128; k++) acc = fmaf(sm[OFF_Z + k], __ldg(&fc1_w[k * 32 + lane]), acc);
        acc = fmaxf(acc, 0.f);
        sm[OFF_Z + 128 + lane] = __ldg(&bn4_g[lane]) * acc * invbn + __ldg(&bn4_b[lane]);
        __syncwarp();
        if (lane < 8) {
            float a = __ldg(&fc2_b[lane]);
            #pragma unroll
            for (int k = 0; k < 32; k++) a = fmaf(sm[OFF_Z + 128 + k], __ldg(&fc2_w[k * 8 + lane]), a);
            a = fmaxf(a, 0.f);
            sm[OFF_Z + 160 + lane] = __ldg(&bn5_g[lane]) * a * invbn + __ldg(&bn5_b[lane]);
        }
        __syncwarp();
        if (lane < 2) {
            float a = __ldg(&fc3_b[lane]);
            #pragma unroll
            for (int k = 0; k < 8; k++) a = fmaf(sm[OFF_Z + 160 + k], __ldg(&fc3_w[k * 2 + lane]), a);
            sm[OFF_Z + 170 + lane] = a;
        }
        __syncwarp();
        if (lane == 0) {
            float l0 = sm[OFF_Z + 170], l1 = sm[OFF_Z + 171];
            float m = fmaxf(l0, l1);
            float lse = m + __logf(__expf(l0 - m) + __expf(l1 - m));
            out[(size_t)b * 2 + 0] = l0 - lse;
            out[(size_t)b * 2 + 1] = l1 - lse;
        }
    }
}

extern "C" void kernel_launch(void* const* d_in, const int* in_sizes, int n_in,
                              void* d_out, int out_size) {
    const float* x     = (const float*)d_in[0];
    const float* adj   = (const float*)d_in[1];
    const float* W1    = (const float*)d_in[2];
    const float* a1s   = (const float*)d_in[3];
    const float* a1d   = (const float*)d_in[4];
    const float* b1    = (const float*)d_in[5];
    const float* W2    = (const float*)d_in[6];
    const float* a2s   = (const float*)d_in[7];
    const float* a2d   = (const float*)d_in[8];
    const float* b2    = (const float*)d_in[9];
    const float* pw1   = (const float*)d_in[10];
    const float* pw2   = (const float*)d_in[11];
    const float* fc1w  = (const float*)d_in[12];
    const float* fc1b  = (const float*)d_in[13];
    const float* fc2w  = (const float*)d_in[14];
    const float* fc2b  = (const float*)d_in[15];
    const float* fc3w  = (const float*)d_in[16];
    const float* fc3b  = (const float*)d_in[17];
    const float* bn4g  = (const float*)d_in[18];
    const float* bn4b  = (const float*)d_in[19];
    const float* bn5g  = (const float*)d_in[20];
    const float* bn5b  = (const float*)d_in[21];
    float* out = (float*)d_out;

    k_pre<<<B_ * 2, 256>>>(x, adj, W1, a1s, a1d);

    const int smem_bytes = SMEM_FLOATS * (int)sizeof(float);
    cudaFuncSetAttribute(nngat_main, cudaFuncAttributeMaxDynamicSharedMemorySize,
                         smem_bytes);
    nngat_main<<<B_, NT, smem_bytes>>>(
        W2, a2s, a2d, b1, b2, pw1, pw2,
        fc1w, fc1b, fc2w, fc2b, fc3w, fc3b, bn4g, bn4b, bn5g, bn5b, out);
}

// round 15
// speedup vs baseline: 1.2972x; 1.0509x over previous
#include <cuda_runtime.h>
#include <math.h>

// ---------------------------------------------------------------------------
// NNGAT_Net, single fused kernel (one CTA per batch, 512 threads, 78.6KB,
// 2 CTAs/SM):
//  Phase A: h = x@W1 (+es/ed) register-tiled GEMM in-smem. W1 staged in the
//           dead HO region; x staged per-16k-chunk into sX[224][17] living in
//           the dead AL/ES/ED region; h written straight to smem (no gmem).
//  Phase B: GAT1 softmax + sparse agg, adjacency>0 ballot inline.
//  Then: topk1 -> augment-adj bitsets -> GAT2 -> topk2 -> readouts -> MLP.
// Output: logp [512*2] | s1 [512*100] | s2 [512*50]
// ---------------------------------------------------------------------------

namespace {
constexpr int B_    = 512;
constexpr int N_    = 200;
constexpr int IND   = 200;
constexpr int D1_   = 32;
constexpr int D2_   = 32;
constexpr int K1_   = 100;
constexpr int K2_   = 50;
constexpr int NT    = 512;          // 16 warps
constexpr int NW    = 16;
constexpr int ALP   = 224;          // padded alpha row (7*32)
constexpr int XP    = 17;           // sX chunk pitch (16 + 1): conflict-free
constexpr int XROWS = 224;          // 7 warp-tiles x 32 rows (200 real + 24 pad)
constexpr float NEGF = -1e9f;

// shared memory layout (float indices)
constexpr int OFF_H     = 0;        // 6400: h1 [200x32]; later xk[100x32], xk2[50x32]@+3200
constexpr int OFF_HO    = 6400;     // 6400: W1 staged (Phase A) -> hout1 -> sH2/sOUT2
constexpr int OFF_AL    = 12800;    // 3584: sX chunk (Phase A, 3808 incl ES/ED overlap);
                                    //       later per-warp alpha rows [16x224]
constexpr int OFF_ES    = 16384;    // 200  (overlapped by sX tail during Phase A)
constexpr int OFF_ED    = 16584;    // 200  (first 24 overlapped during Phase A)
constexpr int OFF_SC    = 16784;    // 200
constexpr int OFF_VAL   = 16984;    // 100
constexpr int OFF_PERM  = 17084;    // 100 (int)
constexpr int OFF_PERM2 = 17184;    // 52  (int)
constexpr int OFF_ADJB  = 17236;    // 1400 (u32): adj bitset [200][7]; later W2 [32x32]
constexpr int OFF_AKB   = 18636;    // 400 (u32)
constexpr int OFF_A2B   = 19036;    // 400 (u32)
constexpr int OFF_Z     = 19436;    // 192
constexpr int OFF_RED   = 19628;    // 32
constexpr int SMEM_FLOATS = 19660;  // 78640 bytes -> 2 CTAs/SM
}

__device__ __forceinline__ float warpMax(float v) {
    #pragma unroll
    for (int o = 16; o > 0; o >>= 1) v = fmaxf(v, __shfl_xor_sync(0xffffffffu, v, o));
    return v;
}
__device__ __forceinline__ float warpSum(float v) {
    #pragma unroll
    for (int o = 16; o > 0; o >>= 1) v += __shfl_xor_sync(0xffffffffu, v, o);
    return v;
}
__device__ __forceinline__ float lrelu02(float x) { return x > 0.f ? x : 0.2f * x; }

__global__ __launch_bounds__(NT, 2)
void nngat_kernel(
    const float* __restrict__ x,     const float* __restrict__ adj,
    const float* __restrict__ W1,    const float* __restrict__ a1s,
    const float* __restrict__ a1d,   const float* __restrict__ b1,
    const float* __restrict__ W2,    const float* __restrict__ a2s,
    const float* __restrict__ a2d,   const float* __restrict__ b2,
    const float* __restrict__ pw1,   const float* __restrict__ pw2,
    const float* __restrict__ fc1_w, const float* __restrict__ fc1_b,
    const float* __restrict__ fc2_w, const float* __restrict__ fc2_b,
    const float* __restrict__ fc3_w, const float* __restrict__ fc3_b,
    const float* __restrict__ bn4_g, const float* __restrict__ bn4_b,
    const float* __restrict__ bn5_g, const float* __restrict__ bn5_b,
    float* __restrict__ out)
{
    extern __shared__ float sm[];
    int*      smi = (int*)sm;
    unsigned* smu = (unsigned*)sm;

    const int b    = blockIdx.x;
    const int tid  = threadIdx.x;
    const int lane = tid & 31;
    const int wid  = tid >> 5;

    const float* xb   = x   + (size_t)b * N_ * IND;
    const float* adjb = adj + (size_t)b * N_ * N_;

    // ---- Phase A setup: W1 into HO; sX pad rows zero; pw norms ----
    float* sX = sm + OFF_AL;          // [224][17]; tail overlaps ES/ED (dead)
    {
        const float4* w4 = (const float4*)W1;
        float4* d4 = (float4*)(sm + OFF_HO);
        for (int t = tid; t < IND * D1_ / 4; t += NT) d4[t] = w4[t];
        for (int t = tid; t < (XROWS - N_) * XP; t += NT)
            sX[N_ * XP + t] = 0.f;
    }
    if (wid == 8) {
        float v = pw1[lane];
        float s = warpSum(v * v);
        if (lane == 0) sm[OFF_RED + 0] = sqrtf(s) + 1e-16f;
    }
    if (wid == 9) {
        float v = pw2[lane];
        float s = warpSum(v * v);
        if (lane == 0) sm[OFF_RED + 1] = sqrtf(s) + 1e-16f;
    }

    // ============ Phase A: h = x @ W1, register-tiled (7 GEMM warps) ========
    const int tr = lane >> 2;   // 0..7 -> 4-row group
    const int tc = lane & 3;    // 0..3 -> 8-col group
    float acc[4][8];
    #pragma unroll
    for (int j = 0; j < 4; j++)
        #pragma unroll
        for (int i = 0; i < 8; i++) acc[j][i] = 0.f;

    const float* sW = sm + OFF_HO;

    for (int c = 0; c < 13; c++) {
        const int k0 = c * 16;
        const int kcnt = (c < 12) ? 16 : 8;
        __syncthreads();    // prior chunk reads done (c=0: W/pad staging done)

        if (c < 12) {       // stage 16 k: 4 float4 per row
            for (int idx = tid; idx < N_ * 4; idx += NT) {
                const int row = idx >> 2, q = idx & 3;
                float4 v = __ldg((const float4*)(xb + (size_t)row * IND + k0) + q);
                float* d = sX + row * XP + 4 * q;
                d[0] = v.x; d[1] = v.y; d[2] = v.z; d[3] = v.w;
            }
        } else {            // last chunk: 8 k
            for (int idx = tid; idx < N_ * 2; idx += NT) {
                const int row = idx >> 1, q = idx & 1;
                float4 v = __ldg((const float4*)(xb + (size_t)row * IND + k0) + q);
                float* d = sX + row * XP + 4 * q;
                d[0] = v.x; d[1] = v.y; d[2] = v.z; d[3] = v.w;
            }
        }
        __syncthreads();

        if (wid < 7) {
            const float* x0 = sX + (wid * 32 + tr * 4) * XP;
            #pragma unroll 4
            for (int k = 0; k < kcnt; k++) {
                const float xv0 = x0[k];
                const float xv1 = x0[XP + k];
                const float xv2 = x0[2 * XP + k];
                const float xv3 = x0[3 * XP + k];
                const float4* wr = (const float4*)(sW + (k0 + k) * D1_);
                const float4 w0 = wr[tc * 2];
                const float4 w1 = wr[tc * 2 + 1];
                acc[0][0] = fmaf(xv0, w0.x, acc[0][0]);
                acc[0][1] = fmaf(xv0, w0.y, acc[0][1]);
                acc[0][2] = fmaf(xv0, w0.z, acc[0][2]);
                acc[0][3] = fmaf(xv0, w0.w, acc[0][3]);
                acc[0][4] = fmaf(xv0, w1.x, acc[0][4]);
                acc[0][5] = fmaf(xv0, w1.y, acc[0][5]);
                acc[0][6] = fmaf(xv0, w1.z, acc[0][6]);
                acc[0][7] = fmaf(xv0, w1.w, acc[0][7]);
                acc[1][0] = fmaf(xv1, w0.x, acc[1][0]);
                acc[1][1] = fmaf(xv1, w0.y, acc[1][1]);
                acc[1][2] = fmaf(xv1, w0.z, acc[1][2]);
                acc[1][3] = fmaf(xv1, w0.w, acc[1][3]);
                acc[1][4] = fmaf(xv1, w1.x, acc[1][4]);
                acc[1][5] = fmaf(xv1, w1.y, acc[1][5]);
                acc[1][6] = fmaf(xv1, w1.z, acc[1][6]);
                acc[1][7] = fmaf(xv1, w1.w, acc[1][7]);
                acc[2][0] = fmaf(xv2, w0.x, acc[2][0]);
                acc[2][1] = fmaf(xv2, w0.y, acc[2][1]);
                acc[2][2] = fmaf(xv2, w0.z, acc[2][2]);
                acc[2][3] = fmaf(xv2, w0.w, acc[2][3]);
                acc[2][4] = fmaf(xv2, w1.x, acc[2][4]);
                acc[2][5] = fmaf(xv2, w1.y, acc[2][5]);
                acc[2][6] = fmaf(xv2, w1.z, acc[2][6]);
                acc[2][7] = fmaf(xv2, w1.w, acc[2][7]);
                acc[3][0] = fmaf(xv3, w0.x, acc[3][0]);
                acc[3][1] = fmaf(xv3, w0.y, acc[3][1]);
                acc[3][2] = fmaf(xv3, w0.z, acc[3][2]);
                acc[3][3] = fmaf(xv3, w0.w, acc[3][3]);
                acc[3][4] = fmaf(xv3, w1.x, acc[3][4]);
                acc[3][5] = fmaf(xv3, w1.y, acc[3][5]);
                acc[3][6] = fmaf(xv3, w1.z, acc[3][6]);
                acc[3][7] = fmaf(xv3, w1.w, acc[3][7]);
            }
        }
    }
    __syncthreads();   // all sX reads done; sX region (incl ES/ED tail) dead

    // epilogue: h -> smem OFF_H; es/ed -> smem (rows >= 200 discarded)
    if (wid < 7) {
        const int c0 = tc * 8;
        float4 s0 = __ldg((const float4*)(a1s + c0));
        float4 s1 = __ldg((const float4*)(a1s + c0 + 4));
        float4 d0 = __ldg((const float4*)(a1d + c0));
        float4 d1 = __ldg((const float4*)(a1d + c0 + 4));
        #pragma unroll
        for (int j = 0; j < 4; j++) {
            const int row = (wid << 5) + (tr << 2) + j;
            float pes = acc[j][0] * s0.x + acc[j][1] * s0.y + acc[j][2] * s0.z + acc[j][3] * s0.w
                      + acc[j][4] * s1.x + acc[j][5] * s1.y + acc[j][6] * s1.z + acc[j][7] * s1.w;
            float ped = acc[j][0] * d0.x + acc[j][1] * d0.y + acc[j][2] * d0.z + acc[j][3] * d0.w
                      + acc[j][4] * d1.x + acc[j][5] * d1.y + acc[j][6] * d1.z + acc[j][7] * d1.w;
            pes += __shfl_xor_sync(0xffffffffu, pes, 1);
            pes += __shfl_xor_sync(0xffffffffu, pes, 2);
            ped += __shfl_xor_sync(0xffffffffu, ped, 1);
            ped += __shfl_xor_sync(0xffffffffu, ped, 2);
            if (row < N_) {
                float* hp = sm + OFF_H + row * D1_ + c0;
                *(float4*)(hp)     = make_float4(acc[j][0], acc[j][1], acc[j][2], acc[j][3]);
                *(float4*)(hp + 4) = make_float4(acc[j][4], acc[j][5], acc[j][6], acc[j][7]);
                if (tc == 0) {
                    sm[OFF_ES + row] = pes;
                    sm[OFF_ED + row] = ped;
                }
            }
        }
    }
    __syncthreads();   // h/es/ed visible; AL region free for alpha rows

    const float b1_l = __ldg(&b1[lane]);

    // ============ Phase B: GAT1 softmax + sparse agg (adj ballot inline) ====
    {
        float* al = sm + OFF_AL + wid * ALP;
        for (int i = wid; i < N_; i += NW) {
            float wv[7];
            #pragma unroll
            for (int c = 0; c < 7; c++) {
                const int j = c * 32 + lane;
                wv[c] = (j < N_) ? adjb[i * N_ + j] : 0.f;
            }
            const float edi = sm[OFF_ED + i];
            unsigned mw[7];
            float alr[7];
            float mx = -INFINITY;
            #pragma unroll
            for (int c = 0; c < 7; c++) {
                const int j = c * 32 + lane;
                unsigned bal = __ballot_sync(0xffffffffu, wv[c] > 0.f);
                if (lane == 0) smu[OFF_ADJB + i * 7 + c] = bal;  // pure adjacency
                if ((i >> 5) == c) bal |= 1u << (i & 31);        // self-loop
                mw[c] = bal;
                float lg = NEGF;
                if ((bal >> lane) & 1u) lg = lrelu02(edi + sm[OFF_ES + j]);
                alr[c] = lg;
                mx = fmaxf(mx, lg);
            }
            mx = warpMax(mx);

            float s = 0.f;
            #pragma unroll
            for (int c = 0; c < 7; c++) {
                float e = __expf(alr[c] - mx);    // masked lanes underflow to 0
                al[c * 32 + lane] = e;            // padded row: in-bounds
                s += e;
            }
            s = warpSum(s);
            const float inv = __fdividef(1.f, s);

            float acc0 = 0.f, acc1 = 0.f, acc2 = 0.f, acc3 = 0.f;
            #pragma unroll
            for (int c = 0; c < 7; c++) {
                unsigned w = mw[c];               // warp-uniform
                const float* hb = sm + OFF_H + c * 32 * D1_ + lane;
                const float* ab = al + c * 32;
                while (w) {
                    const int t0 = __ffs(w) - 1; w &= w - 1;
                    acc0 = fmaf(ab[t0], hb[t0 * D1_], acc0);
                    if (!w) break;
                    const int t1 = __ffs(w) - 1; w &= w - 1;
                    acc1 = fmaf(ab[t1], hb[t1 * D1_], acc1);
                    if (!w) break;
                    const int t2 = __ffs(w) - 1; w &= w - 1;
                    acc2 = fmaf(ab[t2], hb[t2 * D1_], acc2);
                    if (!w) break;
                    const int t3 = __ffs(w) - 1; w &= w - 1;
                    acc3 = fmaf(ab[t3], hb[t3 * D1_], acc3);
                }
            }
            sm[OFF_HO + i * D1_ + lane] = ((acc0 + acc1) + (acc2 + acc3)) * inv + b1_l;
        }
    }
    __syncthreads();

    // ============ Phase C: pool-1 scores ====================================
    {
        const float pw1_l = __ldg(&pw1[lane]);
        const float invn1 = __fdividef(1.f, sm[OFF_RED + 0]);
        for (int i = wid; i < N_; i += NW) {
            float s = warpSum(sm[OFF_HO + i * D1_ + lane] * pw1_l);
            if (lane == 0) sm[OFF_SC + i] = __fdividef(1.f, 1.f + __expf(-s * invn1));
        }
    }
    __syncthreads();

    // stable descending rank == jax.lax.top_k order
    if (tid < N_) {
        const float si = sm[OFF_SC + tid];
        int cnt = 0;
        for (int j = 0; j < N_; j++) {
            const float sj = sm[OFF_SC + j];
            cnt += (sj > si) || (sj == si && j < tid);
        }
        if (cnt < K1_) smi[OFF_PERM + cnt] = tid;
    }
    __syncthreads();

    for (int r = tid; r < K1_; r += NT) {
        float v = sm[OFF_SC + smi[OFF_PERM + r]];
        sm[OFF_VAL + r] = v;
        out[512 * 2 + (size_t)b * K1_ + r] = v;
    }
    __syncthreads();

    // gated xk = hout[perm] * vals  (into dead h1 region)
    for (int t = tid; t < K1_ * D1_; t += NT) {
        const int r = t >> 5, d = t & 31;
        sm[OFF_H + t] = sm[OFF_HO + smi[OFF_PERM + r] * D1_ + d] * sm[OFF_VAL + r];
    }
    __syncthreads();

    // x1 readout partials (warps 0-3)
    if (wid < 4) {
        float mx = -INFINITY, s = 0.f;
        for (int r = wid * 25; r < wid * 25 + 25; r++) {
            float v = sm[OFF_H + r * D1_ + lane];
            mx = fmaxf(mx, v);
            s += v;
        }
        sm[OFF_AL + (wid * 2 + 0) * 32 + lane] = mx;
        sm[OFF_AL + (wid * 2 + 1) * 32 + lane] = s;
    }
    // AKB via warp ballot: lane = pooled column
    for (int r = wid; r < K1_; r += NW) {
        const int pr = smi[OFF_PERM + r];
        const unsigned* arow = smu + OFF_ADJB + pr * 7;
        #pragma unroll
        for (int w = 0; w < 4; w++) {
            const int c = w * 32 + lane;
            bool bit = false;
            if (c < K1_) {
                const int pc = smi[OFF_PERM + c];
                bit = (arow[pc >> 5] >> (pc & 31)) & 1u;
            }
            unsigned bal = __ballot_sync(0xffffffffu, bit);
            if (lane == 0) smu[OFF_AKB + r * 4 + w] = bal;
        }
    }
    __syncthreads();   // ADJB dead from here

    // combine x1 partials; a2 = ak | (ak_nz @ ak_nz); stage W2 into ADJB
    if (tid < 32) {
        float mx = fmaxf(fmaxf(sm[OFF_AL + 0 * 32 + lane], sm[OFF_AL + 2 * 32 + lane]),
                         fmaxf(sm[OFF_AL + 4 * 32 + lane], sm[OFF_AL + 6 * 32 + lane]));
        float s = sm[OFF_AL + 1 * 32 + lane] + sm[OFF_AL + 3 * 32 + lane]
                + sm[OFF_AL + 5 * 32 + lane] + sm[OFF_AL + 7 * 32 + lane];
        sm[OFF_Z + lane]      = mx;
        sm[OFF_Z + 32 + lane] = s * (1.f / K1_);
    }
    for (int t = tid; t < K1_ * 4; t += NT) {
        const int r = t >> 2, w = t & 3;
        unsigned acc2 = smu[OFF_AKB + t];
        #pragma unroll
        for (int kc = 0; kc < 4; kc++) {
            unsigned rw = smu[OFF_AKB + r * 4 + kc];
            while (rw) {
                const int k = __ffs(rw) - 1; rw &= rw - 1;
                acc2 |= smu[OFF_AKB + (kc * 32 + k) * 4 + w];
            }
        }
        smu[OFF_A2B + t] = acc2;
    }
    for (int t = tid; t < D1_ * D2_; t += NT) sm[OFF_ADJB + t] = W2[t];
    __syncthreads();

    // ============ Phase E: GAT2 =============================================
    const float a2s_l = __ldg(&a2s[lane]);
    const float a2d_l = __ldg(&a2d[lane]);
    const float b2_l  = __ldg(&b2[lane]);
    float* sXK   = sm + OFF_H;                 // [100x32]
    float* sH2   = sm + OFF_HO;                // [100x32]
    float* sOUT2 = sm + OFF_HO + K1_ * D2_;    // [100x32]
    float* sW2   = sm + OFF_ADJB;              // [32x32]
    float* sAL2  = sm + OFF_AL;                // [16 x ALP] alpha scratch

    for (int i = wid; i < K1_; i += NW) {
        const float4* xr4 = (const float4*)(sXK + i * D1_);
        float acc1 = 0.f;
        #pragma unroll
        for (int k4 = 0; k4 < D1_ / 4; k4++) {
            float4 xv = xr4[k4];
            const int k = k4 * 4;
            acc1 = fmaf(xv.x, sW2[(k + 0) * D2_ + lane], acc1);
            acc1 = fmaf(xv.y, sW2[(k + 1) * D2_ + lane], acc1);
            acc1 = fmaf(xv.z, sW2[(k + 2) * D2_ + lane], acc1);
            acc1 = fmaf(xv.w, sW2[(k + 3) * D2_ + lane], acc1);
        }
        sH2[i * D2_ + lane] = acc1;
        float es = warpSum(acc1 * a2s_l);
        float ed = warpSum(acc1 * a2d_l);
        if (lane == 0) { sm[OFF_ES + i] = es; sm[OFF_ED + i] = ed; }
    }
    __syncthreads();

    // GAT2 attention + aggregation: 2 rows per warp
    for (int g = wid; g < K1_ / 2; g += NW) {
        const int i0 = 2 * g, i1 = i0 + 1;
        const float ed0 = sm[OFF_ED + i0];
        const float ed1 = sm[OFF_ED + i1];
        float* al2 = sAL2 + wid * ALP;
        float alr0[4], alr1[4];
        float mx0 = -INFINITY, mx1 = -INFINITY;
        #pragma unroll
        for (int c = 0; c < 4; c++) {
            const int j = c * 32 + lane;
            float lg0 = NEGF, lg1 = NEGF;
            if (j < K1_) {
                const float esj = sm[OFF_ES + j];
                const unsigned b0 = smu[OFF_A2B + i0 * 4 + c];
                const unsigned b1w = smu[OFF_A2B + i1 * 4 + c];
                if ((j == i0) || ((b0 >> lane) & 1u))  lg0 = lrelu02(ed0 + esj);
                if ((j == i1) || ((b1w >> lane) & 1u)) lg1 = lrelu02(ed1 + esj);
            }
            alr0[c] = lg0; alr1[c] = lg1;
            mx0 = fmaxf(mx0, lg0); mx1 = fmaxf(mx1, lg1);
        }
        mx0 = warpMax(mx0); mx1 = warpMax(mx1);
        float s0 = 0.f, s1 = 0.f;
        #pragma unroll
        for (int c = 0; c < 4; c++) {
            const int j = c * 32 + lane;
            if (j < K1_) {
                float e0 = __expf(alr0[c] - mx0);
                float e1 = __expf(alr1[c] - mx1);
                al2[j] = e0;
                al2[100 + j] = e1;
                s0 += e0; s1 += e1;
            }
        }
        s0 = warpSum(s0); s1 = warpSum(s1);
        const float inv0 = __fdividef(1.f, s0);
        const float inv1 = __fdividef(1.f, s1);

        const float4* a40 = (const float4*)al2;
        const float4* a41 = (const float4*)(al2 + 100);
        float p00 = 0.f, p01 = 0.f, p02 = 0.f, p03 = 0.f;
        float p10 = 0.f, p11 = 0.f, p12 = 0.f, p13 = 0.f;
        #pragma unroll 5
        for (int j4 = 0; j4 < K1_ / 4; j4++) {
            float4 a0 = a40[j4];
            float4 a1 = a41[j4];
            const int j = j4 * 4;
            float h0 = sH2[(j + 0) * D2_ + lane];
            float h1 = sH2[(j + 1) * D2_ + lane];
            float h2 = sH2[(j + 2) * D2_ + lane];
            float h3 = sH2[(j + 3) * D2_ + lane];
            p00 = fmaf(a0.x, h0, p00); p01 = fmaf(a0.y, h1, p01);
            p02 = fmaf(a0.z, h2, p02); p03 = fmaf(a0.w, h3, p03);
            p10 = fmaf(a1.x, h0, p10); p11 = fmaf(a1.y, h1, p11);
            p12 = fmaf(a1.z, h2, p12); p13 = fmaf(a1.w, h3, p13);
        }
        sOUT2[i0 * D2_ + lane] = ((p00 + p01) + (p02 + p03)) * inv0 + b2_l;
        sOUT2[i1 * D2_ + lane] = ((p10 + p11) + (p12 + p13)) * inv1 + b2_l;
    }
    __syncthreads();

    // ============ Phase F: pool-2 ===========================================
    {
        const float pw2_l = __ldg(&pw2[lane]);
        const float invn2 = __fdividef(1.f, sm[OFF_RED + 1]);
        for (int i = wid; i < K1_; i += NW) {
            float s = warpSum(sOUT2[i * D2_ + lane] * pw2_l);
            if (lane == 0) sm[OFF_SC + i] = __fdividef(1.f, 1.f + __expf(-s * invn2));
        }
    }
    __syncthreads();

    if (tid < K1_) {
        const float si = sm[OFF_SC + tid];
        int cnt = 0;
        for (int j = 0; j < K1_; j++) {
            const float sj = sm[OFF_SC + j];
            cnt += (sj > si) || (sj == si && j < tid);
        }
        if (cnt < K2_) smi[OFF_PERM2 + cnt] = tid;
    }
    __syncthreads();

    for (int r = tid; r < K2_; r += NT) {
        float v = sm[OFF_SC + smi[OFF_PERM2 + r]];
        sm[OFF_VAL + r] = v;
        out[512 * 2 + 512 * K1_ + (size_t)b * K2_ + r] = v;
    }
    __syncthreads();

    float* sXK2 = sm + OFF_H + K1_ * D1_;   // [50x32]
    for (int t = tid; t < K2_ * D2_; t += NT) {
        const int r = t >> 5, d = t & 31;
        sXK2[t] = sOUT2[smi[OFF_PERM2 + r] * D2_ + d] * sm[OFF_VAL + r];
    }
    __syncthreads();

    // x2 readout partials (warps 0-1)
    if (wid < 2) {
        float mx = -INFINITY, s = 0.f;
        for (int r = wid * 25; r < wid * 25 + 25; r++) {
            float v = sXK2[r * D2_ + lane];
            mx = fmaxf(mx, v);
            s += v;
        }
        sm[OFF_AL + (wid * 2 + 0) * 32 + lane] = mx;
        sm[OFF_AL + (wid * 2 + 1) * 32 + lane] = s;
    }
    __syncthreads();
    if (tid < 32) {
        float mx = fmaxf(sm[OFF_AL + 0 * 32 + lane], sm[OFF_AL + 2 * 32 + lane]);
        float s  = sm[OFF_AL + 1 * 32 + lane] + sm[OFF_AL + 3 * 32 + lane];
        sm[OFF_Z + 64 + lane] = mx;
        sm[OFF_Z + 96 + lane] = s * (1.f / K2_);
    }
    __syncthreads();

    // ============ Phase G: MLP head (warp 0) ================================
    if (wid == 0) {
        const float invbn = 1.0f / sqrtf(1.0f + 1e-5f);
        float acc1 = __ldg(&fc1_b[lane]);
        #pragma unroll 4
        for (int k = 0; k < 128; k++) acc1 = fmaf(sm[OFF_Z + k], __ldg(&fc1_w[k * 32 + lane]), acc1);
        acc1 = fmaxf(acc1, 0.f);
        sm[OFF_Z + 128 + lane] = __ldg(&bn4_g[lane]) * acc1 * invbn + __ldg(&bn4_b[lane]);
        __syncwarp();
        if (lane < 8) {
            float a = __ldg(&fc2_b[lane]);
            #pragma unroll
            for (int k = 0; k < 32; k++) a = fmaf(sm[OFF_Z + 128 + k], __ldg(&fc2_w[k * 8 + lane]), a);
            a = fmaxf(a, 0.f);
            sm[OFF_Z + 160 + lane] = __ldg(&bn5_g[lane]) * a * invbn + __ldg(&bn5_b[lane]);
        }
        __syncwarp();
        if (lane < 2) {
            float a = __ldg(&fc3_b[lane]);
            #pragma unroll
            for (int k = 0; k < 8; k++) a = fmaf(sm[OFF_Z + 160 + k], __ldg(&fc3_w[k * 2 + lane]), a);
            sm[OFF_Z + 170 + lane] = a;
        }
        __syncwarp();
        if (lane == 0) {
            float l0 = sm[OFF_Z + 170], l1 = sm[OFF_Z + 171];
            float m = fmaxf(l0, l1);
            float lse = m + __logf(__expf(l0 - m) + __expf(l1 - m));
            out[(size_t)b * 2 + 0] = l0 - lse;
            out[(size_t)b * 2 + 1] = l1 - lse;
        }
    }
}

extern "C" void kernel_launch(void* const* d_in, const int* in_sizes, int n_in,
                              void* d_out, int out_size) {
    const float* x     = (const float*)d_in[0];
    const float* adj   = (const float*)d_in[1];
    const float* W1    = (const float*)d_in[2];
    const float* a1s   = (const float*)d_in[3];
    const float* a1d   = (const float*)d_in[4];
    const float* b1    = (const float*)d_in[5];
    const float* W2    = (const float*)d_in[6];
    const float* a2s   = (const float*)d_in[7];
    const float* a2d   = (const float*)d_in[8];
    const float* b2    = (const float*)d_in[9];
    const float* pw1   = (const float*)d_in[10];
    const float* pw2   = (const float*)d_in[11];
    const float* fc1w  = (const float*)d_in[12];
    const float* fc1b  = (const float*)d_in[13];
    const float* fc2w  = (const float*)d_in[14];
    const float* fc2b  = (const float*)d_in[15];
    const float* fc3w  = (const float*)d_in[16];
    const float* fc3b  = (const float*)d_in[17];
    const float* bn4g  = (const float*)d_in[18];
    const float* bn4b  = (const float*)d_in[19];
    const float* bn5g  = (const float*)d_in[20];
    const float* bn5b  = (const float*)d_in[21];
    float* out = (float*)d_out;

    const int smem_bytes = SMEM_FLOATS * (int)sizeof(float);
    cudaFuncSetAttribute(nngat_kernel, cudaFuncAttributeMaxDynamicSharedMemorySize,
                         smem_bytes);
    nngat_kernel<<<B_, NT, smem_bytes>>>(
        x, adj, W1, a1s, a1d, b1, W2, a2s, a2d, b2, pw1, pw2,
        fc1w, fc1b, fc2w, fc2b, fc3w, fc3b, bn4g, bn4b, bn5g, bn5b, out);
}